// round 3
// baseline (speedup 1.0000x reference)
#include <cuda_runtime.h>

// Chamfer loss: B=4, N=M=8192, D=3.
// loss_b = mean_i min_j ||p_i-g_j||^2  +  mean_j min_i ||g_j-p_i||^2  +  max_i min_j ||p_i-g_j||^2
// out = mean_b loss_b
//
// Decomposition: d_ij = x2_i + (y2_j - 2 x_i . y_j);  min_j d_ij = x2_i + min_j(y2_j - 2 x.y)
// Inner loop uses packed fp32x2 FMA (fma.rn.f32x2) with two x-points per lane-pair.

#define Bsz      4
#define Npts     8192
#define THREADS  256
#define PPT      8                    // x-points per thread (4 f32x2 packs)
#define NSEG     4                    // y-dimension split across blocks
#define SEGLEN   (Npts / NSEG)        // 2048
#define YTILE    512                  // y points per shared tile
#define XCHUNK   (THREADS * PPT)      // 2048 x-points per block
#define NCHUNK   (Npts / XCHUNK)      // 4

// Scratch: partial per-point mins, indexed [z=(b*2+dir)][seg][i]
__device__ float g_partial[2 * Bsz * NSEG * Npts];
__device__ float g_sum[2 * Bsz];   // per (b,dir) sum of mins
__device__ float g_max[Bsz];       // per b max of pred2gt mins

typedef unsigned long long ull;

__device__ __forceinline__ ull pk2(float lo, float hi) {
    ull r; asm("mov.b64 %0, {%1, %2};" : "=l"(r) : "f"(lo), "f"(hi)); return r;
}
__device__ __forceinline__ void upk2(ull v, float& lo, float& hi) {
    asm("mov.b64 {%0, %1}, %2;" : "=f"(lo), "=f"(hi) : "l"(v));
}
__device__ __forceinline__ ull ffma2(ull a, ull b, ull c) {
    ull d; asm("fma.rn.f32x2 %0, %1, %2, %3;" : "=l"(d) : "l"(a), "l"(b), "l"(c)); return d;
}

__global__ void __launch_bounds__(THREADS, 1)
nn_min_kernel(const float* __restrict__ pred, const float* __restrict__ gt)
{
    const int z   = blockIdx.z;      // 0..7 : z = b*2 + dir
    const int b   = z >> 1;
    const int dir = z & 1;
    const float* __restrict__ xp = (dir == 0 ? pred : gt) + (size_t)b * Npts * 3;
    const float* __restrict__ yp = (dir == 0 ? gt : pred) + (size_t)b * Npts * 3;

    const int tid   = threadIdx.x;
    const int xbase = blockIdx.x * XCHUNK;
    const int ybase = blockIdx.y * SEGLEN;

    // Load this thread's 8 x-points; pack coord-pairs for f32x2 math.
    ull cx0[PPT / 2], cx1[PPT / 2], cx2[PPT / 2];
    float x2[PPT];
    #pragma unroll
    for (int m = 0; m < PPT / 2; m++) {
        int iA = xbase + (2 * m    ) * THREADS + tid;
        int iB = xbase + (2 * m + 1) * THREADS + tid;
        float a0 = xp[iA * 3 + 0], a1 = xp[iA * 3 + 1], a2 = xp[iA * 3 + 2];
        float b0 = xp[iB * 3 + 0], b1 = xp[iB * 3 + 1], b2 = xp[iB * 3 + 2];
        cx0[m] = pk2(a0, b0);
        cx1[m] = pk2(a1, b1);
        cx2[m] = pk2(a2, b2);
        x2[2 * m    ] = a0 * a0 + a1 * a1 + a2 * a2;
        x2[2 * m + 1] = b0 * b0 + b1 * b1 + b2 * b2;
    }

    float mn[PPT];
    #pragma unroll
    for (int k = 0; k < PPT; k++) mn[k] = 3.4e38f;

    // y tile, coords pre-scaled by -2 and duplicated into both f32x2 halves:
    // sA[j] = {-2y0,-2y0,-2y1,-2y1}, sB[j] = {-2y2,-2y2, y2n, y2n}
    __shared__ float4 sA[YTILE];
    __shared__ float4 sB[YTILE];

    for (int t0 = 0; t0 < SEGLEN; t0 += YTILE) {
        __syncthreads();
        #pragma unroll
        for (int j = tid; j < YTILE; j += THREADS) {
            int jj = ybase + t0 + j;
            float y0 = yp[jj * 3 + 0], y1 = yp[jj * 3 + 1], y2c = yp[jj * 3 + 2];
            float yn = y0 * y0 + y1 * y1 + y2c * y2c;
            sA[j] = make_float4(-2.f * y0, -2.f * y0, -2.f * y1, -2.f * y1);
            sB[j] = make_float4(-2.f * y2c, -2.f * y2c, yn, yn);
        }
        __syncthreads();

        #pragma unroll 4
        for (int j = 0; j < YTILE; j++) {
            float4 A  = sA[j];
            float4 Bv = sB[j];
            ull ys0 = pk2(A.x, A.y);
            ull ys1 = pk2(A.z, A.w);
            ull ys2 = pk2(Bv.x, Bv.y);
            ull yn  = pk2(Bv.z, Bv.w);
            #pragma unroll
            for (int m = 0; m < PPT / 2; m++) {
                ull acc = ffma2(cx0[m], ys0, yn);
                acc     = ffma2(cx1[m], ys1, acc);
                acc     = ffma2(cx2[m], ys2, acc);
                float lo, hi; upk2(acc, lo, hi);
                mn[2 * m    ] = fminf(mn[2 * m    ], lo);
                mn[2 * m + 1] = fminf(mn[2 * m + 1], hi);
            }
        }
    }

    float* out = g_partial + ((size_t)z * NSEG + blockIdx.y) * Npts;
    #pragma unroll
    for (int k = 0; k < PPT; k++) {
        int i = xbase + k * THREADS + tid;
        out[i] = mn[k] + x2[k];   // add back ||x||^2
    }
}

__global__ void __launch_bounds__(256)
reduce_kernel()
{
    const int z   = blockIdx.x;   // 0..7 : z = b*2 + dir
    const int tid = threadIdx.x;
    const float* base = g_partial + (size_t)z * NSEG * Npts;

    float sum = 0.f, mx = -3.4e38f;
    for (int i = tid; i < Npts; i += 256) {
        float m = base[i];
        #pragma unroll
        for (int s = 1; s < NSEG; s++) m = fminf(m, base[(size_t)s * Npts + i]);
        sum += m;
        mx = fmaxf(mx, m);
    }

    __shared__ float ssum[256];
    __shared__ float smax[256];
    ssum[tid] = sum; smax[tid] = mx;
    __syncthreads();
    for (int o = 128; o > 0; o >>= 1) {
        if (tid < o) {
            ssum[tid] += ssum[tid + o];
            smax[tid]  = fmaxf(smax[tid], smax[tid + o]);
        }
        __syncthreads();
    }
    if (tid == 0) {
        g_sum[z] = ssum[0];
        if ((z & 1) == 0) g_max[z >> 1] = smax[0];   // dir==0 : pred2gt max
    }
}

__global__ void final_kernel(float* out)
{
    if (threadIdx.x == 0) {
        float acc = 0.f;
        for (int b = 0; b < Bsz; b++) {
            float meanP = g_sum[b * 2 + 0] * (1.0f / (float)Npts);  // mean pred2gt
            float meanG = g_sum[b * 2 + 1] * (1.0f / (float)Npts);  // mean gt2pred
            acc += meanP + meanG + g_max[b];                        // gamma=1, beta=1, delta=0
        }
        out[0] = acc * (1.0f / (float)Bsz);
    }
}

extern "C" void kernel_launch(void* const* d_in, const int* in_sizes, int n_in,
                              void* d_out, int out_size)
{
    const float* pred = (const float*)d_in[0];
    const float* gt   = (const float*)d_in[1];

    dim3 grid(NCHUNK, NSEG, 2 * Bsz);     // 4 x 4 x 8 = 128 blocks
    nn_min_kernel<<<grid, THREADS>>>(pred, gt);
    reduce_kernel<<<2 * Bsz, 256>>>();
    final_kernel<<<1, 32>>>((float*)d_out);
}

// round 4
// speedup vs baseline: 1.0202x; 1.0202x over previous
#include <cuda_runtime.h>

// Chamfer loss: B=4, N=M=8192, D=3.
// loss_b = mean_i min_j ||p_i-g_j||^2 + mean_j min_i ||g_j-p_i||^2 + max_i min_j ||p_i-g_j||^2
// out = mean_b loss_b
//
// d_ij = x2_i + (y2_j - 2 x_i.y_j);  min_j d_ij = x2_i + min_j(y2_j - 2 x.y)
// Inner loop: packed fp32x2 FMA (fma.rn.f32x2), two x-points per lane-pair.
// R3 change: NSEG 4->8 (grid 128->256 blocks) + __launch_bounds__(256,2) so each SM
// holds 2 blocks = 16 warps, hiding LDS/RAW latency (issue was 52% at 8 warps/SM).

#define Bsz      4
#define Npts     8192
#define THREADS  256
#define PPT      8                    // x-points per thread (4 f32x2 packs)
#define NSEG     8                    // y-dimension split across blocks
#define SEGLEN   (Npts / NSEG)        // 1024
#define YTILE    512                  // y points per shared tile
#define XCHUNK   (THREADS * PPT)      // 2048 x-points per block
#define NCHUNK   (Npts / XCHUNK)      // 4

// Scratch: partial per-point mins, indexed [z=(b*2+dir)][seg][i]
__device__ float g_partial[2 * Bsz * NSEG * Npts];
__device__ float g_sum[2 * Bsz];   // per (b,dir) sum of mins
__device__ float g_max[Bsz];       // per b max of pred2gt mins

typedef unsigned long long ull;

__device__ __forceinline__ ull pk2(float lo, float hi) {
    ull r; asm("mov.b64 %0, {%1, %2};" : "=l"(r) : "f"(lo), "f"(hi)); return r;
}
__device__ __forceinline__ void upk2(ull v, float& lo, float& hi) {
    asm("mov.b64 {%0, %1}, %2;" : "=f"(lo), "=f"(hi) : "l"(v));
}
__device__ __forceinline__ ull ffma2(ull a, ull b, ull c) {
    ull d; asm("fma.rn.f32x2 %0, %1, %2, %3;" : "=l"(d) : "l"(a), "l"(b), "l"(c)); return d;
}

__global__ void __launch_bounds__(THREADS, 2)
nn_min_kernel(const float* __restrict__ pred, const float* __restrict__ gt)
{
    const int z   = blockIdx.z;      // 0..7 : z = b*2 + dir
    const int b   = z >> 1;
    const int dir = z & 1;
    const float* __restrict__ xp = (dir == 0 ? pred : gt) + (size_t)b * Npts * 3;
    const float* __restrict__ yp = (dir == 0 ? gt : pred) + (size_t)b * Npts * 3;

    const int tid   = threadIdx.x;
    const int xbase = blockIdx.x * XCHUNK;
    const int ybase = blockIdx.y * SEGLEN;

    // Load this thread's 8 x-points; pack coord-pairs for f32x2 math.
    ull cx0[PPT / 2], cx1[PPT / 2], cx2[PPT / 2];
    float x2[PPT];
    #pragma unroll
    for (int m = 0; m < PPT / 2; m++) {
        int iA = xbase + (2 * m    ) * THREADS + tid;
        int iB = xbase + (2 * m + 1) * THREADS + tid;
        float a0 = xp[iA * 3 + 0], a1 = xp[iA * 3 + 1], a2 = xp[iA * 3 + 2];
        float b0 = xp[iB * 3 + 0], b1 = xp[iB * 3 + 1], b2 = xp[iB * 3 + 2];
        cx0[m] = pk2(a0, b0);
        cx1[m] = pk2(a1, b1);
        cx2[m] = pk2(a2, b2);
        x2[2 * m    ] = a0 * a0 + a1 * a1 + a2 * a2;
        x2[2 * m + 1] = b0 * b0 + b1 * b1 + b2 * b2;
    }

    float mn[PPT];
    #pragma unroll
    for (int k = 0; k < PPT; k++) mn[k] = 3.4e38f;

    // y tile as packed f32x2 pairs, coords pre-scaled by -2, duplicated in both halves:
    // sA[j] = {(-2y0,-2y0), (-2y1,-2y1)}, sB[j] = {(-2y2,-2y2), (yn,yn)}
    __shared__ ulonglong2 sA[YTILE];
    __shared__ ulonglong2 sB[YTILE];

    for (int t0 = 0; t0 < SEGLEN; t0 += YTILE) {
        __syncthreads();
        #pragma unroll
        for (int j = tid; j < YTILE; j += THREADS) {
            int jj = ybase + t0 + j;
            float y0 = yp[jj * 3 + 0], y1 = yp[jj * 3 + 1], y2c = yp[jj * 3 + 2];
            float yn = y0 * y0 + y1 * y1 + y2c * y2c;
            sA[j] = make_ulonglong2(pk2(-2.f * y0, -2.f * y0), pk2(-2.f * y1, -2.f * y1));
            sB[j] = make_ulonglong2(pk2(-2.f * y2c, -2.f * y2c), pk2(yn, yn));
        }
        __syncthreads();

        #pragma unroll 4
        for (int j = 0; j < YTILE; j++) {
            ulonglong2 A  = sA[j];   // (ys0, ys1)
            ulonglong2 Bv = sB[j];   // (ys2, yn)
            #pragma unroll
            for (int m = 0; m < PPT / 2; m++) {
                ull acc = ffma2(cx0[m], A.x, Bv.y);
                acc     = ffma2(cx1[m], A.y, acc);
                acc     = ffma2(cx2[m], Bv.x, acc);
                float lo, hi; upk2(acc, lo, hi);
                mn[2 * m    ] = fminf(mn[2 * m    ], lo);
                mn[2 * m + 1] = fminf(mn[2 * m + 1], hi);
            }
        }
    }

    float* out = g_partial + ((size_t)z * NSEG + blockIdx.y) * Npts;
    #pragma unroll
    for (int k = 0; k < PPT; k++) {
        int i = xbase + k * THREADS + tid;
        out[i] = mn[k] + x2[k];   // add back ||x||^2
    }
}

__global__ void __launch_bounds__(256)
reduce_kernel()
{
    const int z   = blockIdx.x;   // 0..7 : z = b*2 + dir
    const int tid = threadIdx.x;
    const float* base = g_partial + (size_t)z * NSEG * Npts;

    float sum = 0.f, mx = -3.4e38f;
    for (int i = tid; i < Npts; i += 256) {
        float m = base[i];
        #pragma unroll
        for (int s = 1; s < NSEG; s++) m = fminf(m, base[(size_t)s * Npts + i]);
        sum += m;
        mx = fmaxf(mx, m);
    }

    __shared__ float ssum[256];
    __shared__ float smax[256];
    ssum[tid] = sum; smax[tid] = mx;
    __syncthreads();
    for (int o = 128; o > 0; o >>= 1) {
        if (tid < o) {
            ssum[tid] += ssum[tid + o];
            smax[tid]  = fmaxf(smax[tid], smax[tid + o]);
        }
        __syncthreads();
    }
    if (tid == 0) {
        g_sum[z] = ssum[0];
        if ((z & 1) == 0) g_max[z >> 1] = smax[0];   // dir==0 : pred2gt max
    }
}

__global__ void final_kernel(float* out)
{
    if (threadIdx.x == 0) {
        float acc = 0.f;
        for (int b = 0; b < Bsz; b++) {
            float meanP = g_sum[b * 2 + 0] * (1.0f / (float)Npts);  // mean pred2gt
            float meanG = g_sum[b * 2 + 1] * (1.0f / (float)Npts);  // mean gt2pred
            acc += meanP + meanG + g_max[b];                        // gamma=1, beta=1, delta=0
        }
        out[0] = acc * (1.0f / (float)Bsz);
    }
}

extern "C" void kernel_launch(void* const* d_in, const int* in_sizes, int n_in,
                              void* d_out, int out_size)
{
    const float* pred = (const float*)d_in[0];
    const float* gt   = (const float*)d_in[1];

    dim3 grid(NCHUNK, NSEG, 2 * Bsz);     // 4 x 8 x 8 = 256 blocks
    nn_min_kernel<<<grid, THREADS>>>(pred, gt);
    reduce_kernel<<<2 * Bsz, 256>>>();
    final_kernel<<<1, 32>>>((float*)d_out);
}